// round 2
// baseline (speedup 1.0000x reference)
#include <cuda_runtime.h>
#include <stdint.h>

// Problem constants (fixed shapes from reference)
#define DET      1024
#define T_TOT    3072                 // DET * 3 replications
#define BATCH    256
#define CLAMP_V  50.0f
#define SOFT_ROW (1025 * 64)          // soft window rows * 64 states

// Edge code: for new state n with predecessor p, the two coded bits are
//   c0 = (n&1) ^ p1 ^ p2 ^ p4 ^ p5
//   c1 = (n&1) ^ p0 ^ p1 ^ p2 ^ p5
// branch metric bm = (1-2c0)*llr0 + (1-2c1)*llr1
//                  = sgn * ( (c0^c1) ? (llr0-llr1) : (llr0+llr1) ),  sgn = 1-2c0
__device__ __forceinline__ void edge_code(int n, int p, float& sgn, int& dif)
{
    int c0 = ((n & 1) ^ (p >> 1) ^ (p >> 2) ^ (p >> 4) ^ (p >> 5)) & 1;
    int c1 = ((n & 1) ^  p       ^ (p >> 1) ^ (p >> 2) ^ (p >> 5)) & 1;
    sgn = c0 ? -1.0f : 1.0f;
    dif = (c0 ^ c1) & 1;
}

// ---------------------------------------------------------------------------
// One block per batch. Warp 0 runs the 3072-step ACS scan (lane l holds
// states l and l+32; both predecessors of any new state live in ONE source
// lane, so the gather is 4 shuffles with no select). Survivor bits for
// t >= 1024 are kept in shared memory; after the scan, all 16 warps run a
// chunked parallel traceback (maps-of-chunks composition) entirely in smem.
// ---------------------------------------------------------------------------
__global__ void __launch_bounds__(512, 1)
wcva_fused(const float* __restrict__ x, const float* __restrict__ w,
           float* __restrict__ dec, float* __restrict__ soft)
{
    __shared__ uint2         sh_prev[2048];     // survivor words, index t-1024
    __shared__ unsigned char sh_map[64][64];    // [chunk][entry] -> exit state
    __shared__ unsigned char sh_entry[64];      // entry state per chunk

    const int b   = blockIdx.x;
    const int tid = threadIdx.x;

    // ------------------------- forward ACS (warp 0) -----------------------
    if (tid < 32) {
        const int l = tid;
        const int h = l >> 1;                   // source lane for state l's preds
        const float2* __restrict__ xrow = (const float2*)(x + (size_t)b * (DET * 2));
        float* __restrict__ softrow = soft + (size_t)b * SOFT_ROW;

        // Per-lane edge sign/selector codes.
        // state l   : preds h (edge0),    h+32 (edge1)
        // state l+32: preds h+16 (edge0), h+48 (edge1)
        float sA0, sA1, sB0, sB1;
        int   dA0, dA1, dB0, dB1;
        edge_code(l,      h,      sA0, dA0);
        edge_code(l,      h + 32, sA1, dA1);
        edge_code(l + 32, h + 16, sB0, dB0);
        edge_code(l + 32, h + 48, sB1, dB1);

        // Carry: u = unclamped, un-meaned path metric; m = mean of carried u.
        // True metric = clip(u - m); clip/sub commute with the shuffle
        // permutation, so they are applied AFTER the gather — the 5-stage
        // butterfly computing m overlaps the next step's gather.
        float ua = (l == 0) ? CLAMP_V : 0.0f;   // state l
        float ub = 0.0f;                        // state l+32
        float m  = 0.0f;

        float2 ll = xrow[0];
        float  wt = w[0];

        for (int t = 0; t < T_TOT; t++) {
            // prefetch next step's inputs (independent of the chain)
            float2 lln = ll;  float wn = wt;
            if (t + 1 < T_TOT) {
                lln = xrow[(t + 1) & (DET - 1)];   // x repeats every DET steps
                wn  = __ldg(w + t + 1);
            }

            // weighted branch metrics (depend only on prefetched ll/wt)
            float wS  = wt * (ll.x + ll.y);
            float wD  = wt * (ll.x - ll.y);
            float wA0 = dA0 ? wD : wS;
            float wA1 = dA1 ? wD : wS;
            float wB0 = dB0 ? wD : wS;
            float wB1 = dB1 ? wD : wS;

            // gather predecessor u's (critical path)
            float gA0 = __shfl_sync(0xffffffffu, ua, h);
            float gA1 = __shfl_sync(0xffffffffu, ub, h);
            float gB0 = __shfl_sync(0xffffffffu, ua, h + 16);
            float gB1 = __shfl_sync(0xffffffffu, ub, h + 16);

            // materialize true metrics: clip(g - m)
            float pA0 = fminf(fmaxf(gA0 - m, -CLAMP_V), CLAMP_V);
            float pA1 = fminf(fmaxf(gA1 - m, -CLAMP_V), CLAMP_V);
            float pB0 = fminf(fmaxf(gB0 - m, -CLAMP_V), CLAMP_V);
            float pB1 = fminf(fmaxf(gB1 - m, -CLAMP_V), CLAMP_V);

            // add-compare-select (fma with ±1 multiplier is exact)
            float cA0 = fmaf(sA0, wA0, pA0);
            float cA1 = fmaf(sA1, wA1, pA1);
            float cB0 = fmaf(sB0, wB0, pB0);
            float cB1 = fmaf(sB1, wB1, pB1);

            ua = fmaxf(cA0, cA1);
            ub = fmaxf(cB0, cB1);
            bool ia = cA1 > cA0;     // argmax: edge 1 only on strict >
            bool ib = cB1 > cB0;

            // mean over 64 states of the NEW u (butterfly; exact *2^-6)
            float s = ua + ub;
            s += __shfl_xor_sync(0xffffffffu, s, 1);
            s += __shfl_xor_sync(0xffffffffu, s, 2);
            s += __shfl_xor_sync(0xffffffffu, s, 4);
            s += __shfl_xor_sync(0xffffffffu, s, 8);
            s += __shfl_xor_sync(0xffffffffu, s, 16);
            m = s * (1.0f / 64.0f);

            // survivor bits -> shared (needed only for t >= 1024)
            unsigned ba = __ballot_sync(0xffffffffu, ia);   // bit l = state l
            unsigned bb = __ballot_sync(0xffffffffu, ib);   // bit l = state l+32
            if (t >= 1024 && l == 0)
                sh_prev[t - 1024] = make_uint2(ba, bb);

            // soft output window t in [1023, 2047]
            if (t >= 1023 && t < 2048) {
                float oa = fminf(fmaxf(ua - m, -CLAMP_V), CLAMP_V);
                float ob = fminf(fmaxf(ub - m, -CLAMP_V), CLAMP_V);
                int r = (t - 1023) * 64;
                softrow[r + l]      = oa;
                softrow[r + l + 32] = ob;
            }

            ll = lln;  wt = wn;
        }
    }
    __syncthreads();

    // --------------------- traceback, all in shared mem -------------------
    // Survivor index s = t - 1024, s = 2047 .. 0 walked downward.
    // Chunk c covers s in [2047-32c .. 2016-32c]; state map composed per chunk.

    // Phase A: 64 chunks x 64 entry states = 4096 independent 32-step traces.
    for (int id = tid; id < 64 * 64; id += 512) {
        int c = id >> 6, e = id & 63;
        int st = e;
        int s0 = 2047 - 32 * c;
        #pragma unroll
        for (int k = 0; k < 32; k++) {
            uint2 wp = sh_prev[s0 - k];
            unsigned sel = (st < 32) ? wp.x : wp.y;
            int ind = (sel >> (st & 31)) & 1;
            st = (st >> 1) + (ind << 5);
        }
        sh_map[c][e] = (unsigned char)st;
    }
    __syncthreads();

    // Phase B: compose chunk maps serially from state 0 at t = T-1.
    if (tid == 0) {
        int st = 0;
        for (int c = 0; c < 64; c++) {
            sh_entry[c] = (unsigned char)st;
            st = sh_map[c][st];
        }
    }
    __syncthreads();

    // Phase C: re-trace output chunks (s < 1024 -> chunks 32..63), emit bits.
    if (tid < 32) {
        int c  = 32 + tid;
        int st = sh_entry[c];
        float* __restrict__ drow = dec + (size_t)b * DET;
        int s0 = 2047 - 32 * c;
        #pragma unroll
        for (int k = 0; k < 32; k++) {
            int s = s0 - k;
            drow[s] = (float)(1 - (st & 1));       // bit from state BEFORE update
            uint2 wp = sh_prev[s];
            unsigned sel = (st < 32) ? wp.x : wp.y;
            int ind = (sel >> (st & 31)) & 1;
            st = (st >> 1) + (ind << 5);
        }
    }
}

// ---------------------------------------------------------------------------
// Harness entry. Output layout: decoded_words (256*1024 f32) then soft
// (256*65600 f32), concatenated.
// ---------------------------------------------------------------------------
extern "C" void kernel_launch(void* const* d_in, const int* in_sizes, int n_in,
                              void* d_out, int out_size)
{
    const float* x  = (const float*)d_in[0];   // (256, 2048)
    const float* wv = (const float*)d_in[1];   // (3072,)
    float* out  = (float*)d_out;

    float* dec  = out;                          // 256*1024
    float* soft = out + (size_t)BATCH * DET;    // 256*65600

    wcva_fused<<<BATCH, 512>>>(x, wv, dec, soft);
}

// round 3
// speedup vs baseline: 1.4429x; 1.4429x over previous
#include <cuda_runtime.h>
#include <stdint.h>

// Problem constants (fixed shapes from reference)
#define DET      1024
#define T_TOT    3072                 // DET * 3 replications
#define BATCH    256
#define CLAMP_V  50.0f
#define SOFT_ROW (1025 * 64)          // soft window rows * 64 states

// Fixed-point scale for the warp-sum (REDUX.SUM is int-only).
#define FPS      262144.0f            // 2^18
#define FPS_INV  (1.0f / (64.0f * 262144.0f))

// Survivor decisions: one byte per (batch, step t-1024, lane).
// bit0 = decision of state l (<32), bit1 = decision of state l+32.  16 MB.
__device__ uint8_t g_sur[(size_t)BATCH * 2048 * 32];
// Per-chunk traceback maps: [batch][chunk(64)][entry(64)] -> exit state. 1 MB.
__device__ uint8_t g_map[(size_t)BATCH * 64 * 64];

// Edge code: for new state n with predecessor p, coded bits are
//   c0 = (n&1) ^ p1 ^ p2 ^ p4 ^ p5 ;  c1 = (n&1) ^ p0 ^ p1 ^ p2 ^ p5
// bm = (1-2c0)*llr0 + (1-2c1)*llr1 = sgn * ((c0^c1) ? (llr0-llr1) : (llr0+llr1))
__device__ __forceinline__ void edge_code(int n, int p, float& sgn, int& dif)
{
    int c0 = ((n & 1) ^ (p >> 1) ^ (p >> 2) ^ (p >> 4) ^ (p >> 5)) & 1;
    int c1 = ((n & 1) ^  p       ^ (p >> 1) ^ (p >> 2) ^ (p >> 5)) & 1;
    sgn = c0 ? -1.0f : 1.0f;
    dif = (c0 ^ c1) & 1;
}

__device__ __forceinline__ float clipf(float v)
{
    return fminf(fmaxf(v, -CLAMP_V), CLAMP_V);
}

// ---------------------------------------------------------------------------
// Forward ACS: one 32-thread block per batch (known-good config). Lane l
// holds states l (ua) and l+32 (ub). Both predecessors of state l live in
// lane l>>1; of state l+32 in lane (l>>1)+16 — 4 shuffles, no selects.
// The carried values are UN-normalized (clip/mean applied at the destination
// after the gather); the mean uses one int REDUX instead of a 5-SHFL tree.
// ---------------------------------------------------------------------------
__global__ void __launch_bounds__(32, 1)
wcva_fwd(const float* __restrict__ x, const float* __restrict__ w,
         float* __restrict__ soft)
{
    const int b = blockIdx.x;
    const int l = threadIdx.x;
    const int h = l >> 1;

    const float2* __restrict__ xrow = (const float2*)(x + (size_t)b * (DET * 2));
    float* __restrict__ softrow = soft + (size_t)b * SOFT_ROW;
    uint8_t* __restrict__ surrow = g_sur + (size_t)b * 2048 * 32 + l;

    // Per-lane edge sign/selector codes.
    // state l   : preds h (edge0),    h+32 (edge1)
    // state l+32: preds h+16 (edge0), h+48 (edge1)
    float sA0, sA1, sB0, sB1;
    int   dA0, dA1, dB0, dB1;
    edge_code(l,      h,      sA0, dA0);
    edge_code(l,      h + 32, sA1, dA1);
    edge_code(l + 32, h + 16, sB0, dB0);
    edge_code(l + 32, h + 48, sB1, dB1);

    float ua = (l == 0) ? CLAMP_V : 0.0f;   // state l      (un-normalized)
    float ub = 0.0f;                        // state l+32
    float m  = 0.0f;                        // mean to subtract at use-time

    float2 ll = xrow[0];
    float  wt = w[0];

    for (int t = 0; t < T_TOT; t++) {
        // prefetch next step's inputs (off-chain)
        float2 lln = ll;  float wn = wt;
        if (t + 1 < T_TOT) {
            lln = xrow[(t + 1) & (DET - 1)];   // x repeats every DET steps
            wn  = __ldg(w + t + 1);
        }

        // weighted branch metrics (off-chain)
        float wS  = wt * (ll.x + ll.y);
        float wD  = wt * (ll.x - ll.y);
        float wA0 = dA0 ? wD : wS;
        float wA1 = dA1 ? wD : wS;
        float wB0 = dB0 ? wD : wS;
        float wB1 = dB1 ? wD : wS;

        // gather predecessor (un-normalized) metrics — overlaps the m-chain
        float gA0 = __shfl_sync(0xffffffffu, ua, h);
        float gA1 = __shfl_sync(0xffffffffu, ub, h);
        float gB0 = __shfl_sync(0xffffffffu, ua, h + 16);
        float gB1 = __shfl_sync(0xffffffffu, ub, h + 16);

        // materialize true metrics: clip(g - m)   (m from previous step)
        float pA0 = clipf(gA0 - m);
        float pA1 = clipf(gA1 - m);
        float pB0 = clipf(gB0 - m);
        float pB1 = clipf(gB1 - m);

        // add-compare-select (fma with ±1 multiplier is exact)
        float cA0 = fmaf(sA0, wA0, pA0);
        float cA1 = fmaf(sA1, wA1, pA1);
        float cB0 = fmaf(sB0, wB0, pB0);
        float cB1 = fmaf(sB1, wB1, pB1);

        float nua = fmaxf(cA0, cA1);
        float nub = fmaxf(cB0, cB1);
        bool  ia  = cA1 > cA0;     // argmax: edge 1 only on strict >
        bool  ib  = cB1 > cB0;

        // mean over 64 states via one int REDUX (fixed point 2^18)
        int si = __float2int_rn((nua + nub) * FPS);
        int ss = __reduce_add_sync(0xffffffffu, si);
        m = (float)ss * FPS_INV;

        // survivor byte (only needed for t >= 1024); bit0=ia, bit1=ib
        if (t >= 1024)
            surrow[(size_t)(t - 1024) * 32] = (uint8_t)((ia ? 1 : 0) | (ib ? 2 : 0));

        // soft output window t in [1023, 2047]
        if (t >= 1023 && t < 2048) {
            int r = (t - 1023) * 64;
            softrow[r + l]      = clipf(nua - m);
            softrow[r + l + 32] = clipf(nub - m);
        }

        ua = nua;  ub = nub;  ll = lln;  wt = wn;
    }
}

// ---------------------------------------------------------------------------
// Traceback phase A: per (batch, chunk) build the 64-entry state map over
// 32 survivor steps. Chunk c covers s = 2047-32c .. 2016-32c (descending).
// One 64-thread block per (batch, chunk); survivor rows staged in smem.
// ---------------------------------------------------------------------------
__global__ void __launch_bounds__(64)
tb_maps()
{
    __shared__ uint8_t rows[1024];     // 32 steps x 32 lanes

    const int b = blockIdx.x >> 6;
    const int c = blockIdx.x & 63;
    const int s0 = 2047 - 32 * c;      // top (first-processed) row

    const uint4* __restrict__ src =
        (const uint4*)(g_sur + (((size_t)b * 2048) + (s0 - 31)) * 32);
    ((uint4*)rows)[threadIdx.x] = src[threadIdx.x];   // 64 x 16B = 1 KB
    __syncthreads();

    int st = threadIdx.x;              // entry state
#pragma unroll
    for (int k = 0; k < 32; k++) {
        uint8_t byt = rows[(31 - k) * 32 + (st & 31)];   // row s0-k
        int ind = (byt >> (st >> 5)) & 1;
        st = (st >> 1) + (ind << 5);
    }
    g_map[((size_t)b << 12) + (c << 6) + threadIdx.x] = (uint8_t)st;
}

// ---------------------------------------------------------------------------
// Traceback phase B+C: per batch, compose the 64 chunk maps serially from
// state 0 at t = T-1, then re-trace the 32 output chunks (s < 1024) in
// parallel and emit decoded bits. Everything staged in shared memory.
// ---------------------------------------------------------------------------
__global__ void __launch_bounds__(256)
tb_emit(float* __restrict__ dec)
{
    __shared__ uint8_t smap[4096];     // 64 chunks x 64 entries
    __shared__ uint8_t ssur[32768];    // survivor bytes for s in [0, 1024)
    __shared__ uint8_t sentry[64];

    const int b   = blockIdx.x;
    const int tid = threadIdx.x;

    ((uint4*)smap)[tid] = ((const uint4*)(g_map + ((size_t)b << 12)))[tid];

    const uint4* __restrict__ ss = (const uint4*)(g_sur + (size_t)b * 2048 * 32);
#pragma unroll
    for (int i = 0; i < 8; i++)
        ((uint4*)ssur)[tid + 256 * i] = ss[tid + 256 * i];
    __syncthreads();

    if (tid == 0) {
        int st = 0;
        for (int c = 0; c < 64; c++) {
            sentry[c] = (uint8_t)st;
            st = smap[(c << 6) + st];
        }
    }
    __syncthreads();

    if (tid < 32) {
        int c  = 32 + tid;             // output chunks: s0 = 1023-32*tid
        int st = sentry[c];
        float* __restrict__ drow = dec + (size_t)b * DET;
        int s0 = 2047 - 32 * c;
#pragma unroll
        for (int k = 0; k < 32; k++) {
            int s = s0 - k;
            drow[s] = (float)(1 - (st & 1));     // bit from state BEFORE update
            uint8_t byt = ssur[s * 32 + (st & 31)];
            int ind = (byt >> (st >> 5)) & 1;
            st = (st >> 1) + (ind << 5);
        }
    }
}

// ---------------------------------------------------------------------------
// Harness entry. Output layout: decoded_words (256*1024 f32) then soft
// (256*65600 f32), concatenated.
// ---------------------------------------------------------------------------
extern "C" void kernel_launch(void* const* d_in, const int* in_sizes, int n_in,
                              void* d_out, int out_size)
{
    const float* x  = (const float*)d_in[0];   // (256, 2048)
    const float* wv = (const float*)d_in[1];   // (3072,)
    float* out  = (float*)d_out;

    float* dec  = out;                          // 256*1024
    float* soft = out + (size_t)BATCH * DET;    // 256*65600

    wcva_fwd<<<BATCH, 32>>>(x, wv, soft);
    tb_maps<<<BATCH * 64, 64>>>();
    tb_emit<<<BATCH, 256>>>(dec);
}

// round 6
// speedup vs baseline: 1.6735x; 1.1598x over previous
#include <cuda_runtime.h>
#include <stdint.h>

// Problem constants (fixed shapes from reference)
#define DET      1024
#define T_TOT    3072                 // DET * 3 replications
#define BATCH    256
#define CLAMP_V  50.0f
#define SOFT_ROW (1025 * 64)          // soft window rows * 64 states

// Survivor decisions: one byte per (batch, step t-1024, lane).
// bit0 = decision of state l (<32), bit1 = decision of state l+32.  16 MB.
__device__ uint8_t g_sur[(size_t)BATCH * 2048 * 32];
// Per-chunk traceback maps: [batch][chunk(64)][entry(64)] -> exit state. 1 MB.
__device__ uint8_t g_map[(size_t)BATCH * 64 * 64];

// Edge code: for new state n with predecessor p, coded bits are
//   c0 = (n&1) ^ p1 ^ p2 ^ p4 ^ p5 ;  c1 = (n&1) ^ p0 ^ p1 ^ p2 ^ p5
// bm = (1-2c0)*llr0 + (1-2c1)*llr1 = sgn * ((c0^c1) ? (llr0-llr1) : (llr0+llr1))
__device__ __forceinline__ void edge_code(int n, int p, float& sgn, int& dif)
{
    int c0 = ((n & 1) ^ (p >> 1) ^ (p >> 2) ^ (p >> 4) ^ (p >> 5)) & 1;
    int c1 = ((n & 1) ^  p       ^ (p >> 1) ^ (p >> 2) ^ (p >> 5)) & 1;
    sgn = c0 ? -1.0f : 1.0f;
    dif = (c0 ^ c1) & 1;
}

__device__ __forceinline__ float clipf(float v)
{
    return fminf(fmaxf(v, -CLAMP_V), CLAMP_V);
}

// Warp sum broadcast, 2 shuffle rounds (radix 8 then radix 4).
// All shuffles within a round are independent (only round latency is serial).
// Grouping is xor-symmetric + commutative -> bit-identical result on every
// lane (uniform mean across all 64 states).
__device__ __forceinline__ float warp_sum_r84(float s0)
{
    float x1 = __shfl_xor_sync(0xffffffffu, s0, 1);
    float x2 = __shfl_xor_sync(0xffffffffu, s0, 2);
    float x3 = __shfl_xor_sync(0xffffffffu, s0, 3);
    float x4 = __shfl_xor_sync(0xffffffffu, s0, 4);
    float x5 = __shfl_xor_sync(0xffffffffu, s0, 5);
    float x6 = __shfl_xor_sync(0xffffffffu, s0, 6);
    float x7 = __shfl_xor_sync(0xffffffffu, s0, 7);
    float s1 = ((s0 + x1) + (x2 + x3)) + ((x4 + x5) + (x6 + x7));
    float y8  = __shfl_xor_sync(0xffffffffu, s1, 8);
    float y16 = __shfl_xor_sync(0xffffffffu, s1, 16);
    float y24 = __shfl_xor_sync(0xffffffffu, s1, 24);
    return (s1 + y8) + (y16 + y24);
}

// One full ACS step. Carried: va/vb = UNNORMALIZED max-results of the
// previous step, s = their warp sum. Destination applies the zero-lag
// normalization p = clip(fma(-1/64, s, g)) — exact reference semantics
// (s/64 is exact; fma = single rounding of v - m; clip every step).
// Produces new va/vb (unnormalized), new s, and the two decision bits.
#define ACS_STEP(IA, IB)                                                     \
    float wS  = wt * (ll.x + ll.y);                                          \
    float wD  = wt * (ll.x - ll.y);                                          \
    float wA0 = dA0 ? wD : wS;                                               \
    float wA1 = dA1 ? wD : wS;                                               \
    float wB0 = dB0 ? wD : wS;                                               \
    float wB1 = dB1 ? wD : wS;                                               \
    float gA0 = __shfl_sync(0xffffffffu, va, h);                             \
    float gA1 = __shfl_sync(0xffffffffu, vb, h);                             \
    float gB0 = __shfl_sync(0xffffffffu, va, h + 16);                        \
    float gB1 = __shfl_sync(0xffffffffu, vb, h + 16);                        \
    float pA0 = clipf(fmaf(-0.015625f, s, gA0));                             \
    float pA1 = clipf(fmaf(-0.015625f, s, gA1));                             \
    float pB0 = clipf(fmaf(-0.015625f, s, gB0));                             \
    float pB1 = clipf(fmaf(-0.015625f, s, gB1));                             \
    float cA0 = fmaf(sA0, wA0, pA0);                                         \
    float cA1 = fmaf(sA1, wA1, pA1);                                         \
    float cB0 = fmaf(sB0, wB0, pB0);                                         \
    float cB1 = fmaf(sB1, wB1, pB1);                                         \
    float nva = fmaxf(cA0, cA1);                                             \
    float nvb = fmaxf(cB0, cB1);                                             \
    bool  IA  = cA1 > cA0;                                                   \
    bool  IB  = cB1 > cB0;                                                   \
    va = nva;  vb = nvb;                                                     \
    s  = warp_sum_r84(nva + nvb);                                            \
    ll = lln;  wt = wn;

// ---------------------------------------------------------------------------
// Forward ACS: one 32-thread block per batch. Lane l holds states l (va) and
// l+32 (vb); predecessors of state l live in lane l>>1, of l+32 in (l>>1)+16.
// ---------------------------------------------------------------------------
__global__ void __launch_bounds__(32, 1)
wcva_fwd(const float* __restrict__ x, const float* __restrict__ w,
         float* __restrict__ soft)
{
    const int b = blockIdx.x;
    const int l = threadIdx.x;
    const int h = l >> 1;

    const float2* __restrict__ xrow = (const float2*)(x + (size_t)b * (DET * 2));
    float* __restrict__ softrow = soft + (size_t)b * SOFT_ROW;
    uint8_t* __restrict__ surrow = g_sur + (size_t)b * 2048 * 32 + l;

    float sA0, sA1, sB0, sB1;
    int   dA0, dA1, dB0, dB1;
    edge_code(l,      h,      sA0, dA0);
    edge_code(l,      h + 32, sA1, dA1);
    edge_code(l + 32, h + 16, sB0, dB0);
    edge_code(l + 32, h + 48, sB1, dB1);

    // Carried state: unnormalized v, its warp sum s.
    // s = 0 makes step 0 consume in_prob0 raw, exactly like the reference.
    float va = (l == 0) ? CLAMP_V : 0.0f;   // state l
    float vb = 0.0f;                        // state l+32
    float s  = 0.0f;

    float2 ll = xrow[0];
    float  wt = w[0];

    // ---- segment 1: t in [0, 1024)  (no outputs) ----
#pragma unroll 2
    for (int t = 0; t < 1024; t++) {
        float2 lln = xrow[(t + 1) & (DET - 1)];
        float  wn  = __ldg(w + t + 1);
        ACS_STEP(ia_, ib_)
        (void)ia_; (void)ib_;
    }

    // ---- segment 2: t in [1024, 2049) ----
    // Every iteration: soft row for step t-1 (in [1023, 2047]) from the OLD
    // carried (va, vb, s), then the ACS step, then the survivor byte for t.
#pragma unroll 2
    for (int t = 1024; t < 2049; t++) {
        float2 lln = xrow[(t + 1) & (DET - 1)];
        float  wn  = __ldg(w + t + 1);

        // soft output of step t-1 (same formula as the decision-path p)
        {
            int r = (t - 1024) * 64;
            softrow[r + l]      = clipf(fmaf(-0.015625f, s, va));
            softrow[r + l + 32] = clipf(fmaf(-0.015625f, s, vb));
        }

        ACS_STEP(ia, ib)

        surrow[(size_t)(t - 1024) * 32] =
            (uint8_t)((ia ? 1 : 0) | (ib ? 2 : 0));
    }

    // ---- segment 3: t in [2049, T_TOT)  (survivor bytes only) ----
#pragma unroll 2
    for (int t = 2049; t < T_TOT; t++) {
        int tn = (t + 1 < T_TOT) ? t + 1 : t;
        float2 lln = xrow[tn & (DET - 1)];
        float  wn  = __ldg(w + tn);
        ACS_STEP(ia, ib)
        surrow[(size_t)(t - 1024) * 32] =
            (uint8_t)((ia ? 1 : 0) | (ib ? 2 : 0));
    }
}

// ---------------------------------------------------------------------------
// Traceback phase A: per (batch, chunk) build the 64-entry state map over
// 32 survivor steps. Chunk c covers s = 2047-32c .. 2016-32c (descending).
// ---------------------------------------------------------------------------
__global__ void __launch_bounds__(64)
tb_maps()
{
    __shared__ uint8_t rows[1024];     // 32 steps x 32 lanes

    const int b = blockIdx.x >> 6;
    const int c = blockIdx.x & 63;
    const int s0 = 2047 - 32 * c;      // top (first-processed) row

    const uint4* __restrict__ src =
        (const uint4*)(g_sur + (((size_t)b * 2048) + (s0 - 31)) * 32);
    ((uint4*)rows)[threadIdx.x] = src[threadIdx.x];   // 64 x 16B = 1 KB
    __syncthreads();

    int st = threadIdx.x;              // entry state
#pragma unroll
    for (int k = 0; k < 32; k++) {
        uint8_t byt = rows[(31 - k) * 32 + (st & 31)];   // row s0-k
        int ind = (byt >> (st >> 5)) & 1;
        st = (st >> 1) + (ind << 5);
    }
    g_map[((size_t)b << 12) + (c << 6) + threadIdx.x] = (uint8_t)st;
}

// ---------------------------------------------------------------------------
// Traceback phase B+C: per batch, compose chunk maps serially from state 0
// at t = T-1, then re-trace the 32 output chunks (s < 1024) and emit bits.
// ---------------------------------------------------------------------------
__global__ void __launch_bounds__(256)
tb_emit(float* __restrict__ dec)
{
    __shared__ uint8_t smap[4096];     // 64 chunks x 64 entries
    __shared__ uint8_t ssur[32768];    // survivor bytes for s in [0, 1024)
    __shared__ uint8_t sentry[64];

    const int b   = blockIdx.x;
    const int tid = threadIdx.x;

    ((uint4*)smap)[tid] = ((const uint4*)(g_map + ((size_t)b << 12)))[tid];

    const uint4* __restrict__ ss = (const uint4*)(g_sur + (size_t)b * 2048 * 32);
#pragma unroll
    for (int i = 0; i < 8; i++)
        ((uint4*)ssur)[tid + 256 * i] = ss[tid + 256 * i];
    __syncthreads();

    if (tid == 0) {
        int st = 0;
        for (int c = 0; c < 64; c++) {
            sentry[c] = (uint8_t)st;
            st = smap[(c << 6) + st];
        }
    }
    __syncthreads();

    if (tid < 32) {
        int c  = 32 + tid;             // output chunks: s0 = 1023-32*tid
        int st = sentry[c];
        float* __restrict__ drow = dec + (size_t)b * DET;
        int s0 = 2047 - 32 * c;
#pragma unroll
        for (int k = 0; k < 32; k++) {
            int s = s0 - k;
            drow[s] = (float)(1 - (st & 1));     // bit from state BEFORE update
            uint8_t byt = ssur[s * 32 + (st & 31)];
            int ind = (byt >> (st >> 5)) & 1;
            st = (st >> 1) + (ind << 5);
        }
    }
}

// ---------------------------------------------------------------------------
// Harness entry. Output layout: decoded_words (256*1024 f32) then soft
// (256*65600 f32), concatenated.
// ---------------------------------------------------------------------------
extern "C" void kernel_launch(void* const* d_in, const int* in_sizes, int n_in,
                              void* d_out, int out_size)
{
    const float* x  = (const float*)d_in[0];   // (256, 2048)
    const float* wv = (const float*)d_in[1];   // (3072,)
    float* out  = (float*)d_out;

    float* dec  = out;                          // 256*1024
    float* soft = out + (size_t)BATCH * DET;    // 256*65600

    wcva_fwd<<<BATCH, 32>>>(x, wv, soft);
    tb_maps<<<BATCH * 64, 64>>>();
    tb_emit<<<BATCH, 256>>>(dec);
}